// round 12
// baseline (speedup 1.0000x reference)
#include <cuda_runtime.h>

// SSKernelNPLR: H=256, N=64, c=1, rank=1, L=2048.
// R11: single fused kernel. Grid 512 x 256: two blocks per head, each does
// the Cauchy+Woodbury for half the spectrum (packed f32x2 across 2 nodes,
// R9 inner loop). The second block to finish a head (per-head atomic) runs
// that head's c2r half-length radix-4 inverse FFT. Overlaps the latency-
// bound FFT with the FMA-bound Cauchy chip-wide; kills the second launch.

#define NSTATE 64
#define LFULL  2048
#define MHALF  1024

typedef unsigned long long u64;

__device__ float2 g_spec[256 * 1025];   // 2.05 MB scratch spectrum
__device__ int    g_done[256];          // zero-init; winner resets to 0

__device__ __forceinline__ u64 pk2(float lo, float hi) {
    u64 r; asm("mov.b64 %0,{%1,%2};" : "=l"(r) : "f"(lo), "f"(hi)); return r;
}
__device__ __forceinline__ void up2(u64 v, float& lo, float& hi) {
    asm("mov.b64 {%0,%1},%2;" : "=f"(lo), "=f"(hi) : "l"(v));
}
__device__ __forceinline__ u64 add2(u64 a, u64 b) {
    u64 r; asm("add.rn.f32x2 %0,%1,%2;" : "=l"(r) : "l"(a), "l"(b)); return r;
}
__device__ __forceinline__ u64 mul2(u64 a, u64 b) {
    u64 r; asm("mul.rn.f32x2 %0,%1,%2;" : "=l"(r) : "l"(a), "l"(b)); return r;
}
__device__ __forceinline__ u64 ffma2(u64 a, u64 b, u64 c) {
    u64 r; asm("fma.rn.f32x2 %0,%1,%2,%3;" : "=l"(r) : "l"(a), "l"(b), "l"(c)); return r;
}
__device__ __forceinline__ float frcp(float x) {
    float r; asm("rcp.approx.f32 %0,%1;" : "=f"(r) : "f"(x)); return r;
}
__device__ __forceinline__ float2 cmul(float2 a, float2 b) {
    return make_float2(a.x * b.x - a.y * b.y, a.x * b.y + a.y * b.x);
}

__global__ __launch_bounds__(256)
void ssk_fused_kernel(const float* __restrict__ Cin,
                      const float* __restrict__ Bin,
                      const float* __restrict__ Pin,
                      const float* __restrict__ Win,
                      const float* __restrict__ log_dt,
                      float* __restrict__ out)
{
    // Cauchy operands (used in phase A only)
    __shared__ ulonglong2 sv[NSTATE][5];
    // FFT buffers (used in phase B only)
    __shared__ float2 X[MHALF];        // 8 KB
    __shared__ float2 Y[MHALF];        // 8 KB
    __shared__ float2 T[768];          // 6 KB
    __shared__ int s_win;

    const int bid  = blockIdx.x;
    const int h    = bid >> 1;
    const int half = bid & 1;          // which 512-node half
    const int tid  = threadIdx.x;      // 0..255
    const float dt = expf(log_dt[h]);

    // ---- stage per-head operands ----
    if (tid < NSTATE) {
        const int base = (h * NSTATE + tid) * 2;
        float2 b = make_float2(Bin[base], Bin[base + 1]);
        float2 c = make_float2(Cin[base], Cin[base + 1]);
        float2 p = make_float2(Pin[base], Pin[base + 1]);
        float2 q = make_float2(p.x, -p.y);          // Q = conj(P)
        float wdx = -Win[base] * dt, wdy = -Win[base + 1] * dt;
        sv[tid][0] = make_ulonglong2(pk2(wdx, wdx), pk2(wdy, wdy));
        float2 v;
        v = cmul(b, c); sv[tid][1] = make_ulonglong2(pk2(v.x, v.x), pk2(v.y, v.y));
        v = cmul(b, q); sv[tid][2] = make_ulonglong2(pk2(v.x, v.x), pk2(v.y, v.y));
        v = cmul(p, c); sv[tid][3] = make_ulonglong2(pk2(v.x, v.x), pk2(v.y, v.y));
        float v11 = p.x * p.x + p.y * p.y;          // P*conj(P) is real
        sv[tid][4] = make_ulonglong2(pk2(v11, v11), 0ull);
    }
    __syncthreads();

    // ---- phase A: Cauchy + Woodbury, 2 packed nodes/thread ----
    float zxs[2], zys[2];
    float2 facv[2];
    #pragma unroll
    for (int k = 0; k < 2; k++) {
        const int f = half * 512 + k * 256 + tid;   // 0..1023
        float s, c;
        sincospif((float)f * (1.0f / MHALF), &s, &c);
        float2 om = make_float2(c, -s);             // exp(-2*pi*i*f/L)
        float ex = 1.0f + om.x, ey = om.y;          // 1 + omega
        float inv_e2 = frcp(ex * ex + ey * ey);
        float ax = 1.0f - om.x, ay = -om.y;         // 1 - omega
        zxs[k] = 2.0f * (ax * ex + ay * ey) * inv_e2;
        zys[k] = 2.0f * (ay * ex - ax * ey) * inv_e2;
        facv[k] = make_float2(2.0f * ex * inv_e2, -2.0f * ey * inv_e2);
    }
    const u64 zxp = pk2(zxs[0], zxs[1]);
    const u64 zyp = pk2(zys[0], zys[1]);

    u64 re0 = 0, re1 = 0, re2 = 0, re3 = 0;
    u64 ia0 = 0, ia1 = 0, ia2 = 0;
    u64 ib0 = 0, ib1 = 0, ib2 = 0, ib3 = 0;

    #pragma unroll 4
    for (int n = 0; n < NSTATE; n++) {
        const ulonglong2 q0 = sv[n][0];
        const ulonglong2 q1 = sv[n][1];
        const ulonglong2 q2 = sv[n][2];
        const ulonglong2 q3 = sv[n][3];
        const ulonglong2 q4 = sv[n][4];
        u64 dxp = add2(zxp, q0.x);                  // z.re - w_dt.re (both nodes)
        u64 dyp = add2(zyp, q0.y);
        u64 nr  = mul2(dxp, dxp);
        nr = ffma2(dyp, dyp, nr);
        float n0, n1; up2(nr, n0, n1);
        u64 rp  = pk2(frcp(n0), frcp(n1));
        u64 urp = mul2(dxp, rp);                    // 1/d = ur - i*ui
        u64 uip = mul2(dyp, rp);
        re0 = ffma2(q1.x, urp, re0); re0 = ffma2(q1.y, uip, re0);
        re1 = ffma2(q2.x, urp, re1); re1 = ffma2(q2.y, uip, re1);
        re2 = ffma2(q3.x, urp, re2); re2 = ffma2(q3.y, uip, re2);
        re3 = ffma2(q4.x, urp, re3);
        ia0 = ffma2(q1.y, urp, ia0);
        ia1 = ffma2(q2.y, urp, ia1);
        ia2 = ffma2(q3.y, urp, ia2);
        ib0 = ffma2(q1.x, uip, ib0);
        ib1 = ffma2(q2.x, uip, ib1);
        ib2 = ffma2(q3.x, uip, ib2);
        ib3 = ffma2(q4.x, uip, ib3);
    }

    float reh[4][2], iah[3][2], ibh[4][2];
    up2(re0, reh[0][0], reh[0][1]); up2(re1, reh[1][0], reh[1][1]);
    up2(re2, reh[2][0], reh[2][1]); up2(re3, reh[3][0], reh[3][1]);
    up2(ia0, iah[0][0], iah[0][1]); up2(ia1, iah[1][0], iah[1][1]);
    up2(ia2, iah[2][0], iah[2][1]);
    up2(ib0, ibh[0][0], ibh[0][1]); up2(ib1, ibh[1][0], ibh[1][1]);
    up2(ib2, ibh[2][0], ibh[2][1]); up2(ib3, ibh[3][0], ibh[3][1]);

    #pragma unroll
    for (int k = 0; k < 2; k++) {
        const int f = half * 512 + k * 256 + tid;
        float2 r00 = make_float2(dt * reh[0][k], dt * (iah[0][k] - ibh[0][k]));
        float2 r01 = make_float2(dt * reh[1][k], dt * (iah[1][k] - ibh[1][k]));
        float2 r10 = make_float2(dt * reh[2][k], dt * (iah[2][k] - ibh[2][k]));
        float2 r11 = make_float2(dt * reh[3][k], dt * (-ibh[3][k]));
        // num = r00 - r01*r10/(1+r11)
        float2 t = cmul(r01, r10);
        float2 d = make_float2(1.0f + r11.x, r11.y);
        float iD = frcp(d.x * d.x + d.y * d.y);
        float2 t2 = make_float2((t.x * d.x + t.y * d.y) * iD,
                                (t.y * d.x - t.x * d.y) * iD);
        float2 kf = cmul(make_float2(r00.x - t2.x, r00.y - t2.y), facv[k]);
        g_spec[h * 1025 + f] = kf;
    }

    // f = 1024 (omega = -1 analytic limit): k_f = 0.5*dt*sum_n v00
    if (half == 0 && tid == 0) {
        float sx = 0.f, sy = 0.f;
        #pragma unroll 8
        for (int n = 0; n < NSTATE; n++) {
            float vx, vy, du;
            up2(sv[n][1].x, vx, du);
            up2(sv[n][1].y, vy, du);
            sx += vx; sy += vy;
        }
        g_spec[h * 1025 + 1024] = make_float2(0.5f * dt * sx, 0.5f * dt * sy);
    }

    // ---- release + elect winner (canonical threadFenceReduction pattern) ----
    __threadfence();            // all threads: publish g_spec writes
    __syncthreads();
    if (tid == 0) {
        int old = atomicAdd(&g_done[h], 1);
        s_win = (old == 1);
        if (old == 1) g_done[h] = 0;    // reset for next graph replay
    }
    __syncthreads();
    if (!s_win) return;

    // ---- phase B (winner only): c2r iFFT via 1024-pt radix-4 Stockham ----
    for (int j = tid; j < 768; j += 256) {
        float s, c;
        sincospif((float)j * (1.0f / 512.0f), &s, &c);   // angle = 2*pi*j/1024
        T[j] = make_float2(c, s);
    }
    // pack: Z[k] = E + i*W*O,  E = S[k]+conj(S[1024-k]), O = S[k]-conj(S[1024-k]),
    // W = exp(+i*pi*k/1024).  k==0 uses real parts of bins 0 and 1024 only.
    const float2* spec = g_spec + h * 1025;
    #pragma unroll
    for (int j = 0; j < 4; j++) {
        int k = tid + j * 256;
        float2 Xa = spec[k];
        float2 Xm = spec[MHALF - k];
        if (k == 0) { Xa.y = 0.0f; Xm.y = 0.0f; }
        float Ex = Xa.x + Xm.x,  Ey = Xa.y - Xm.y;
        float Ox = Xa.x - Xm.x,  Oy = Xa.y + Xm.y;
        float s, c;
        sincospif((float)k * (1.0f / MHALF), &s, &c);    // angle = pi*k/1024
        X[k] = make_float2(Ex - (c * Oy + s * Ox), Ey + (c * Ox - s * Oy));
    }
    __syncthreads();

    // radix-4 Stockham, stages m = 1,4,16,64,256
    float2* src = X;
    float2* dst = Y;
    #pragma unroll
    for (int m = 1; m <= 256; m <<= 2) {
        int jm = tid & ~(m - 1);
        int r  = tid & (m - 1);
        float2 u0 = src[tid];
        float2 u1 = src[tid + 256];
        float2 u2 = src[tid + 512];
        float2 u3 = src[tid + 768];
        float2 e  = make_float2(u0.x + u2.x, u0.y + u2.y);
        float2 o  = make_float2(u0.x - u2.x, u0.y - u2.y);
        float2 ep = make_float2(u1.x + u3.x, u1.y + u3.y);
        float2 op = make_float2(u1.x - u3.x, u1.y - u3.y);
        float2 iop = make_float2(-op.y, op.x);            // i*(u1-u3)
        float2 w1 = T[jm];
        float2 w2 = T[2 * jm];
        float2 w3 = T[3 * jm];
        int base = 4 * jm + r;
        dst[base]         = make_float2(e.x + ep.x, e.y + ep.y);
        dst[base + m]     = cmul(w1, make_float2(o.x + iop.x, o.y + iop.y));
        dst[base + 2 * m] = cmul(w2, make_float2(e.x - ep.x, e.y - ep.y));
        dst[base + 3 * m] = cmul(w3, make_float2(o.x - iop.x, o.y - iop.y));
        __syncthreads();
        float2* tmp = src; src = dst; dst = tmp;
    }

    // z[n] = out[2n] + i*out[2n+1]  -> coalesced float2 store
    const float scale = 1.0f / (float)LFULL;
    float2* o2 = (float2*)(out + (size_t)h * LFULL);
    #pragma unroll
    for (int j = 0; j < 4; j++) {
        int n = tid + j * 256;
        float2 z = src[n];
        o2[n] = make_float2(z.x * scale, z.y * scale);
    }
}

extern "C" void kernel_launch(void* const* d_in, const int* in_sizes, int n_in,
                              void* d_out, int out_size)
{
    (void)in_sizes; (void)n_in; (void)out_size;
    const float* C  = (const float*)d_in[0];
    const float* B  = (const float*)d_in[1];
    const float* P  = (const float*)d_in[2];
    const float* W  = (const float*)d_in[3];
    const float* ld = (const float*)d_in[4];
    float* out = (float*)d_out;
    ssk_fused_kernel<<<512, 256>>>(C, B, P, W, ld, out);
}

// round 15
// speedup vs baseline: 1.0830x; 1.0830x over previous
#include <cuda_runtime.h>

// SSKernelNPLR: H=256, N=64, c=1, rank=1, L=2048.
// R12 (resubmit after infra failure):
//  K1: exact R8 cauchy (best measured, ~19.9us): 1024 blocks x 128 thr,
//      2 nodes/thread, scalar front-end + ffma2 accumulation, LDS.128 operands.
//  K2: radix-4 Stockham c2r iFFT, 1 head per 256-thread block, grid=256
//      (2 independent blocks/SM on most SMs -> latency interleaving).

#define NSTATE 64
#define LFULL  2048
#define MHALF  1024

typedef unsigned long long u64;

__device__ float2 g_spec[256 * 1025];   // 2.05 MB scratch spectrum

__device__ __forceinline__ u64 pk2(float lo, float hi) {
    u64 r; asm("mov.b64 %0,{%1,%2};" : "=l"(r) : "f"(lo), "f"(hi)); return r;
}
__device__ __forceinline__ void up2(u64 v, float& lo, float& hi) {
    asm("mov.b64 {%0,%1},%2;" : "=f"(lo), "=f"(hi) : "l"(v));
}
__device__ __forceinline__ u64 ffma2(u64 a, u64 b, u64 c) {
    u64 r; asm("fma.rn.f32x2 %0,%1,%2,%3;" : "=l"(r) : "l"(a), "l"(b), "l"(c)); return r;
}
__device__ __forceinline__ float frcp(float x) {
    float r; asm("rcp.approx.f32 %0,%1;" : "=f"(r) : "f"(x)); return r;
}
__device__ __forceinline__ float2 cmul(float2 a, float2 b) {
    return make_float2(a.x * b.x - a.y * b.y, a.x * b.y + a.y * b.x);
}

// ---------------- K1: Cauchy + Woodbury (R8 exact) ----------------
__global__ __launch_bounds__(128)
void cauchy_kernel(const float* __restrict__ Cin,
                   const float* __restrict__ Bin,
                   const float* __restrict__ Pin,
                   const float* __restrict__ Win,
                   const float* __restrict__ log_dt)
{
    // interleaved operands: sv2[n] = { {a0,b0}, {a1,b1}, {a2,b2}, {a3,wd} }
    // aX = pk(vX.x, -vX.x), bX = pk(vX.y, vX.y), wd = pk(-w.x*dt, -w.y*dt)
    __shared__ ulonglong2 sv2[NSTATE][4];

    const int bid   = blockIdx.x;
    const int h     = bid >> 2;
    const int chunk = bid & 3;
    const int tid   = threadIdx.x;     // 0..127
    const float dt  = expf(log_dt[h]);

    if (tid < NSTATE) {
        const int base = (h * NSTATE + tid) * 2;
        float2 b = make_float2(Bin[base], Bin[base + 1]);
        float2 c = make_float2(Cin[base], Cin[base + 1]);
        float2 p = make_float2(Pin[base], Pin[base + 1]);
        float2 q = make_float2(p.x, -p.y);          // Q = conj(P)
        u64 wd = pk2(-Win[base] * dt, -Win[base + 1] * dt);
        float2 v;
        v = cmul(b, c);
        sv2[tid][0] = make_ulonglong2(pk2(v.x, -v.x), pk2(v.y, v.y));
        v = cmul(b, q);
        sv2[tid][1] = make_ulonglong2(pk2(v.x, -v.x), pk2(v.y, v.y));
        v = cmul(p, c);
        sv2[tid][2] = make_ulonglong2(pk2(v.x, -v.x), pk2(v.y, v.y));
        float v11 = p.x * p.x + p.y * p.y;          // P*conj(P) is real
        sv2[tid][3] = make_ulonglong2(pk2(v11, -v11), wd);
    }
    __syncthreads();

    // two frequency nodes per thread: f = chunk*256 + k*128 + tid
    float zx[2], zy[2];
    float2 facv[2];
    #pragma unroll
    for (int k = 0; k < 2; k++) {
        const int f = chunk * 256 + k * 128 + tid;  // 0..1023
        float s, c;
        sincospif((float)f * (1.0f / MHALF), &s, &c);
        float2 om = make_float2(c, -s);             // exp(-2*pi*i*f/L)
        float ex = 1.0f + om.x, ey = om.y;          // 1 + omega
        float inv_e2 = frcp(ex * ex + ey * ey);
        float ax = 1.0f - om.x, ay = -om.y;         // 1 - omega
        zx[k] = 2.0f * (ax * ex + ay * ey) * inv_e2;
        zy[k] = 2.0f * (ay * ex - ax * ey) * inv_e2;
        facv[k] = make_float2(2.0f * ex * inv_e2, -2.0f * ey * inv_e2);
    }

    u64 acc[2][4];
    #pragma unroll
    for (int k = 0; k < 2; k++)
        #pragma unroll
        for (int a = 0; a < 4; a++) acc[k][a] = 0ull;

    #pragma unroll 4
    for (int n = 0; n < NSTATE; n++) {
        const ulonglong2 p0 = sv2[n][0];
        const ulonglong2 p1 = sv2[n][1];
        const ulonglong2 p2 = sv2[n][2];
        const ulonglong2 p3 = sv2[n][3];
        float wdx, wdy; up2(p3.y, wdx, wdy);
        #pragma unroll
        for (int k = 0; k < 2; k++) {
            float dx = zx[k] + wdx;                 // z - w*dt (pre-negated)
            float dy = zy[k] + wdy;
            float r  = frcp(dx * dx + dy * dy);
            float ur = dx * r, ui = dy * r;         // 1/d = (ur, -ui)
            u64 P1 = pk2(ur, ui);
            u64 P2 = pk2(ui, ur);
            acc[k][0] = ffma2(p0.x, P1, acc[k][0]); acc[k][0] = ffma2(p0.y, P2, acc[k][0]);
            acc[k][1] = ffma2(p1.x, P1, acc[k][1]); acc[k][1] = ffma2(p1.y, P2, acc[k][1]);
            acc[k][2] = ffma2(p2.x, P1, acc[k][2]); acc[k][2] = ffma2(p2.y, P2, acc[k][2]);
            acc[k][3] = ffma2(p3.x, P1, acc[k][3]); // v11 real: no imag term
        }
    }

    #pragma unroll
    for (int k = 0; k < 2; k++) {
        const int f = chunk * 256 + k * 128 + tid;
        float2 r00, r01, r10, r11;
        up2(acc[k][0], r00.x, r00.y); up2(acc[k][1], r01.x, r01.y);
        up2(acc[k][2], r10.x, r10.y); up2(acc[k][3], r11.x, r11.y);
        r00.x *= dt; r00.y *= dt;  r01.x *= dt; r01.y *= dt;
        r10.x *= dt; r10.y *= dt;  r11.x *= dt; r11.y *= dt;
        // num = r00 - r01*r10/(1+r11)
        float2 t = cmul(r01, r10);
        float2 d = make_float2(1.0f + r11.x, r11.y);
        float iD = frcp(d.x * d.x + d.y * d.y);
        float2 t2 = make_float2((t.x * d.x + t.y * d.y) * iD,
                                (t.y * d.x - t.x * d.y) * iD);
        float2 kf = cmul(make_float2(r00.x - t2.x, r00.y - t2.y), facv[k]);
        g_spec[h * 1025 + f] = kf;
    }

    // f = 1024 (omega = -1 analytic limit): k_f = 0.5*dt*sum_n v00
    if (chunk == 0 && tid == 0) {
        float sx = 0.f, sy = 0.f;
        #pragma unroll 8
        for (int n = 0; n < NSTATE; n++) {
            float vx, vxn, vy, du;
            up2(sv2[n][0].x, vx, vxn);
            up2(sv2[n][0].y, vy, du);
            sx += vx; sy += vy;
        }
        g_spec[h * 1025 + 1024] = make_float2(0.5f * dt * sx, 0.5f * dt * sy);
    }
}

// ---------------- K2: c2r iFFT via radix-4 Stockham, 1 head/block ----------------
__global__ __launch_bounds__(256)
void ifft_kernel(float* __restrict__ out)
{
    __shared__ float2 X[MHALF];        // ping (8 KB)
    __shared__ float2 Y[MHALF];        // pong (8 KB)
    __shared__ float2 T[768];          // exp(+2*pi*i*j/1024), j<768 (6 KB)

    const int tid = threadIdx.x;       // 0..255
    const int h   = blockIdx.x;

    for (int j = tid; j < 768; j += 256) {
        float s, c;
        sincospif((float)j * (1.0f / 512.0f), &s, &c);   // angle = 2*pi*j/1024
        T[j] = make_float2(c, s);
    }

    // pack: Z[k] = E + i*W*O,  E = S[k]+conj(S[1024-k]), O = S[k]-conj(S[1024-k]),
    // W = exp(+i*pi*k/1024).  k==0 uses real parts of bins 0 and 1024 only.
    const float2* spec = g_spec + h * 1025;
    #pragma unroll
    for (int j = 0; j < 4; j++) {
        int k = tid + j * 256;
        float2 Xa = spec[k];
        float2 Xm = spec[MHALF - k];
        if (k == 0) { Xa.y = 0.0f; Xm.y = 0.0f; }
        float Ex = Xa.x + Xm.x,  Ey = Xa.y - Xm.y;
        float Ox = Xa.x - Xm.x,  Oy = Xa.y + Xm.y;
        float s, c;
        sincospif((float)k * (1.0f / MHALF), &s, &c);    // angle = pi*k/1024
        X[k] = make_float2(Ex - (c * Oy + s * Ox), Ey + (c * Ox - s * Oy));
    }
    __syncthreads();

    // 1024-pt inverse complex FFT: radix-4 Stockham, stages m = 1,4,16,64,256.
    float2* src = X;
    float2* dst = Y;
    #pragma unroll
    for (int m = 1; m <= 256; m <<= 2) {
        int jm = tid & ~(m - 1);
        int r  = tid & (m - 1);
        float2 u0 = src[tid];
        float2 u1 = src[tid + 256];
        float2 u2 = src[tid + 512];
        float2 u3 = src[tid + 768];
        float2 e  = make_float2(u0.x + u2.x, u0.y + u2.y);
        float2 o  = make_float2(u0.x - u2.x, u0.y - u2.y);
        float2 ep = make_float2(u1.x + u3.x, u1.y + u3.y);
        float2 op = make_float2(u1.x - u3.x, u1.y - u3.y);
        float2 iop = make_float2(-op.y, op.x);            // i*(u1-u3)
        float2 w1 = T[jm];
        float2 w2 = T[2 * jm];
        float2 w3 = T[3 * jm];
        int base = 4 * jm + r;
        dst[base]         = make_float2(e.x + ep.x, e.y + ep.y);
        dst[base + m]     = cmul(w1, make_float2(o.x + iop.x, o.y + iop.y));
        dst[base + 2 * m] = cmul(w2, make_float2(e.x - ep.x, e.y - ep.y));
        dst[base + 3 * m] = cmul(w3, make_float2(o.x - iop.x, o.y - iop.y));
        __syncthreads();
        float2* tmp = src; src = dst; dst = tmp;
    }

    // z[n] = out[2n] + i*out[2n+1]  -> coalesced float2 store
    const float scale = 1.0f / (float)LFULL;
    float2* o2 = (float2*)(out + (size_t)h * LFULL);
    #pragma unroll
    for (int j = 0; j < 4; j++) {
        int n = tid + j * 256;
        float2 z = src[n];
        o2[n] = make_float2(z.x * scale, z.y * scale);
    }
}

extern "C" void kernel_launch(void* const* d_in, const int* in_sizes, int n_in,
                              void* d_out, int out_size)
{
    (void)in_sizes; (void)n_in; (void)out_size;
    const float* C  = (const float*)d_in[0];
    const float* B  = (const float*)d_in[1];
    const float* P  = (const float*)d_in[2];
    const float* W  = (const float*)d_in[3];
    const float* ld = (const float*)d_in[4];
    float* out = (float*)d_out;
    cauchy_kernel<<<1024, 128>>>(C, B, P, W, ld);
    ifft_kernel<<<256, 256>>>(out);
}